// round 16
// baseline (speedup 1.0000x reference)
#include <cuda_runtime.h>
#include <cuda_bf16.h>
#include <cuda_fp16.h>
#include <math.h>
#include <stdint.h>

#define T_SEQ 4096
#define DM    2048
#define NH    8
#define NKV   4
#define HD    256
#define WIN   1024
#define QKVS  4096     // fused row: Q[0,2048) | K[2048,3072) | V[3072,4096)
#define SMAX  8.0f     // fixed softmax max: |s| <= 16 provable, exp(16-8) < fp16 max

// Scratch (static __device__ arrays — allocation-free per harness rules)
__device__ __half g_qkvh[T_SEQ * QKVS];       // 32 MB fused QKV (fp16, post norm+rope)
__device__ __half g_xh[T_SEQ * DM];           // 16 MB
__device__ __half g_wqkvh[QKVS * DM];         // 16 MB [Wq; Wk; Wv]
__device__ __half g_woh[DM * DM];             // 8 MB
__device__ __half g_yh[T_SEQ * DM];           // 16 MB (attention out, fp16)
__device__ float  g_cs[T_SEQ * 128];          // rope cos table
__device__ float  g_sn[T_SEQ * 128];          // rope sin table

__device__ __forceinline__ uint32_t pack_f16x2(float lo, float hi) {
    __half2 h = __floats2half2_rn(lo, hi);    // .x = lo (low 16 bits)
    return *reinterpret_cast<uint32_t*>(&h);
}

__device__ __forceinline__ uint32_t smem_u32(const void* p) {
    uint32_t a;
    asm("{ .reg .u64 t; cvta.to.shared.u64 t, %1; cvt.u32.u64 %0, t; }"
        : "=r"(a) : "l"(p));
    return a;
}
__device__ __forceinline__ void cp_async16(uint32_t dst, const void* src) {
    asm volatile("cp.async.cg.shared.global [%0], [%1], 16;" :: "r"(dst), "l"(src));
}
__device__ __forceinline__ void cp_commit() {
    asm volatile("cp.async.commit_group;" ::: "memory");
}
__device__ __forceinline__ void cp_wait1() {
    asm volatile("cp.async.wait_group 1;" ::: "memory");
}

#define MMA_F16(d0,d1,d2,d3,a0,a1,a2,a3,b0,b1)                               \
    asm volatile(                                                            \
        "mma.sync.aligned.m16n8k16.row.col.f32.f16.f16.f32 "                 \
        "{%0,%1,%2,%3}, {%4,%5,%6,%7}, {%8,%9}, {%0,%1,%2,%3};"              \
        : "+f"(d0), "+f"(d1), "+f"(d2), "+f"(d3)                             \
        : "r"(a0), "r"(a1), "r"(a2), "r"(a3), "r"(b0), "r"(b1))

#define LDSM_X4(r0,r1,r2,r3,addr)                                            \
    asm volatile("ldmatrix.sync.aligned.m8n8.x4.shared.b16 {%0,%1,%2,%3}, [%4];" \
        : "=r"(r0), "=r"(r1), "=r"(r2), "=r"(r3) : "r"(addr))

// ---------------------------------------------------------------------------
// ONE kernel: fp32->fp16 convert of x/Wq/Wk/Wv/Wo  +  rope cos/sin table.
// Blocks [0, CONV_BLOCKS) convert; blocks beyond build the table (2 t each).
// ---------------------------------------------------------------------------
#define NX   (T_SEQ * DM)
#define NWQ  (DM * DM)
#define NWK  (NKV * HD * DM)
#define NWV  (NKV * HD * DM)
#define NWO  (DM * DM)
#define NTOT (NX + NWQ + NWK + NWV + NWO)
#define CONV_BLOCKS 2048
#define PREP_BLOCKS (CONV_BLOCKS + T_SEQ / 2)

__global__ __launch_bounds__(256) void prep_kernel(
    const float* __restrict__ x,  const float* __restrict__ Wq,
    const float* __restrict__ Wk, const float* __restrict__ Wv,
    const float* __restrict__ Wo, const int* __restrict__ pos,
    __half* __restrict__ xh, __half* __restrict__ wqkvh,
    __half* __restrict__ woh, float* __restrict__ cs, float* __restrict__ sn)
{
    if (blockIdx.x < CONV_BLOCKS) {
        for (size_t i = ((size_t)blockIdx.x * 256 + threadIdx.x) * 8; i < NTOT;
             i += (size_t)CONV_BLOCKS * 256 * 8) {
            const float* src;
            __half* dst;
            size_t o = i;
            if (o < NX)                { src = x;  dst = xh; }
            else if ((o -= NX)  < NWQ) { src = Wq; dst = wqkvh; }
            else if ((o -= NWQ) < NWK) { src = Wk; dst = wqkvh + NWQ; }
            else if ((o -= NWK) < NWV) { src = Wv; dst = wqkvh + NWQ + NWK; }
            else { o -= NWV;             src = Wo; dst = woh; }
            float4 v0 = *(const float4*)(src + o);
            float4 v1 = *(const float4*)(src + o + 4);
            uint4 ov;
            ov.x = pack_f16x2(v0.x, v0.y);
            ov.y = pack_f16x2(v0.z, v0.w);
            ov.z = pack_f16x2(v1.x, v1.y);
            ov.w = pack_f16x2(v1.z, v1.w);
            *(uint4*)((char*)dst + o * 2) = ov;
        }
    } else {
        int b = blockIdx.x - CONV_BLOCKS;
        int t = b * 2 + (threadIdx.x >> 7);
        int f = threadIdx.x & 127;
        float inv_freq = expf(-(float)f * (logf(10000.0f) / 128.0f));
        float ang = (float)pos[t] * inv_freq;
        float sv, cv;
        sincosf(ang, &sv, &cv);
        cs[t * 128 + f] = cv;
        sn[t * 128 + f] = sv;
    }
}

// ---------------------------------------------------------------------------
// Fused QKV GEMM + RMSNorm + RoPE epilogue.
// C[4096 rows][4096 cols] = xh @ wqkvh^T, tile 128x256 (BN = one full head),
// BK=64, 512 threads = 16 warps (4m x 4n), warp tile 32x64, cp.async double
// buffered, ldmatrix fragments. Q/K-region tiles (bcol<3072) apply
// RMSNorm (per-row over the 256-col head, on fp32 accumulators) + RoPE
// before the fp16 store; V tiles store raw fp16.
// ---------------------------------------------------------------------------
#define QG_STW_A   (128 * 36)
#define QG_STW_B   (256 * 36)
#define QG_STAGE   (QG_STW_A + QG_STW_B)
#define QG_SMEM_BYTES (2 * QG_STAGE * 4)     // 110592

__global__ __launch_bounds__(512, 1) void qkv_gemm_fused(
    const __half* __restrict__ A, const __half* __restrict__ B,
    __half* __restrict__ Cq,
    const float* __restrict__ qw, const float* __restrict__ kw,
    const float* __restrict__ cs, const float* __restrict__ sn_t)
{
    extern __shared__ uint32_t sm[];
    const int K    = DM;
    const int tid  = threadIdx.x;
    const int brow = blockIdx.y * 128;
    const int bcol = blockIdx.x * 256;
    const int warp = tid >> 5;
    const int lane = tid & 31;
    const int g    = lane >> 2;
    const int tig  = lane & 3;
    const int warpM = (warp >> 2) * 32;
    const int warpN = (warp & 3) * 64;
    const int nslab = K >> 6;

    const uint32_t sa = smem_u32(sm);
    const uint32_t aab = sa + 4u * ((warpM + (lane & 15)) * 36 + ((lane >> 4) << 2));
    const uint32_t bbb = sa + 4u * (QG_STW_A
                       + (warpN + (lane & 7) + ((lane >> 4) << 3)) * 36
                       + (((lane >> 3) & 1) << 2));

    auto As_w = [&](int st, int r, int w) -> uint32_t& {
        return sm[st * QG_STAGE + r * 36 + w];
    };
    auto Bs_w = [&](int st, int r, int w) -> uint32_t& {
        return sm[st * QG_STAGE + QG_STW_A + r * 36 + w];
    };

    auto load_slab = [&](int j, int st) {
        const int k0 = j << 6;
#pragma unroll
        for (int i = 0; i < 2; i++) {          // A: 1024 granules
            int id  = tid + i * 512;
            int row = id >> 3;
            int g8  = (id & 7) * 8;
            cp_async16(smem_u32(&As_w(st, row, g8 >> 1)),
                       A + (size_t)(brow + row) * K + k0 + g8);
        }
#pragma unroll
        for (int i = 0; i < 4; i++) {          // B: 2048 granules
            int id  = tid + i * 512;
            int row = id >> 3;
            int g8  = (id & 7) * 8;
            cp_async16(smem_u32(&Bs_w(st, row, g8 >> 1)),
                       B + (size_t)(bcol + row) * K + k0 + g8);
        }
    };

    float acc[2][8][4];
#pragma unroll
    for (int mi = 0; mi < 2; mi++)
#pragma unroll
        for (int nj = 0; nj < 8; nj++)
#pragma unroll
            for (int c = 0; c < 4; c++) acc[mi][nj][c] = 0.f;

    load_slab(0, 0);
    cp_commit();

    for (int j = 0; j < nslab; j++) {
        const int st = j & 1;
        if (j + 1 < nslab) load_slab(j + 1, st ^ 1);
        cp_commit();
        cp_wait1();
        __syncthreads();

        const uint32_t stoff = (uint32_t)st * (QG_STAGE * 4);
#pragma unroll
        for (int ks = 0; ks < 32; ks += 8) {
            uint32_t af[2][4];
            uint32_t bf[8][2];
            LDSM_X4(af[0][0], af[0][1], af[0][2], af[0][3],
                    aab + stoff + 4u * ks);
            LDSM_X4(af[1][0], af[1][1], af[1][2], af[1][3],
                    aab + stoff + 4u * (16 * 36) + 4u * ks);
#pragma unroll
            for (int njp = 0; njp < 4; njp++)
                LDSM_X4(bf[2 * njp][0], bf[2 * njp][1],
                        bf[2 * njp + 1][0], bf[2 * njp + 1][1],
                        bbb + stoff + (uint32_t)njp * (16 * 36 * 4) + 4u * ks);
#pragma unroll
            for (int mi = 0; mi < 2; mi++)
#pragma unroll
                for (int nj = 0; nj < 8; nj++)
                    MMA_F16(acc[mi][nj][0], acc[mi][nj][1],
                            acc[mi][nj][2], acc[mi][nj][3],
                            af[mi][0], af[mi][1], af[mi][2], af[mi][3],
                            bf[nj][0], bf[nj][1]);
        }
        __syncthreads();
    }

    if (bcol < 3072) {
        // ---- fused RMSNorm + RoPE epilogue (Q or K head tile) ----
        const float* wgt = (bcol < 2048) ? qw : kw;

        // per-thread partial sum of squares for the 4 owned rows
        float p[4] = {0.f, 0.f, 0.f, 0.f};
#pragma unroll
        for (int nj = 0; nj < 8; nj++) {
            p[0] += acc[0][nj][0] * acc[0][nj][0] + acc[0][nj][1] * acc[0][nj][1];
            p[1] += acc[0][nj][2] * acc[0][nj][2] + acc[0][nj][3] * acc[0][nj][3];
            p[2] += acc[1][nj][0] * acc[1][nj][0] + acc[1][nj][1] * acc[1][nj][1];
            p[3] += acc[1][nj][2] * acc[1][nj][2] + acc[1][nj][3] * acc[1][nj][3];
        }
#pragma unroll
        for (int o = 1; o <= 2; o <<= 1) {
#pragma unroll
            for (int i = 0; i < 4; i++)
                p[i] += __shfl_xor_sync(0xffffffffu, p[i], o);
        }
        float* part = (float*)sm;              // [4 n-warps][128 rows]
        const int wn4 = warp & 3;
        if (tig == 0) {
            part[wn4 * 128 + warpM + g]      = p[0];
            part[wn4 * 128 + warpM + 8 + g]  = p[1];
            part[wn4 * 128 + warpM + 16 + g] = p[2];
            part[wn4 * 128 + warpM + 24 + g] = p[3];
        }
        __syncthreads();

        float scale[4];
        int   trow[4];
#pragma unroll
        for (int i = 0; i < 4; i++) {
            int r = warpM + i * 8 + g;
            float tot = part[r] + part[128 + r] + part[256 + r] + part[384 + r];
            scale[i] = rsqrtf(tot * (1.0f / HD) + 1e-6f);
            trow[i]  = brow + r;
        }

#pragma unroll
        for (int nj = 0; nj < 8; nj++) {
            int d  = warpN + nj * 8 + tig * 2;   // head-dim position (0..255)
            int f  = d & 127;
            float w0 = wgt[d], w1 = wgt[d + 1];
#pragma unroll
            for (int i = 0; i < 4; i++) {
                // rows i=0..3 map to acc[(i>>1)][nj][(i&1)*2 + {0,1}]
                float a0 = acc[i >> 1][nj][(i & 1) * 2];
                float a1 = acc[i >> 1][nj][(i & 1) * 2 + 1];
                float n0 = a0 * scale[i] * w0;
                float n1 = a1 * scale[i] * w1;
                float2 c2 = *(const float2*)(cs   + trow[i] * 128 + f);
                float2 s2 = *(const float2*)(sn_t + trow[i] * 128 + f);
                float r0 = n0 * c2.x - n1 * s2.x;
                float r1 = n1 * c2.y + n0 * s2.y;
                *(uint32_t*)(Cq + (size_t)trow[i] * QKVS + bcol + d) =
                    pack_f16x2(r0, r1);
            }
        }
    } else {
        // ---- V tile: plain fp16 store ----
#pragma unroll
        for (int mi = 0; mi < 2; mi++) {
            int row0 = brow + warpM + mi * 16 + g;
#pragma unroll
            for (int nj = 0; nj < 8; nj++) {
                int col = bcol + warpN + nj * 8 + tig * 2;
                *(uint32_t*)(Cq + (size_t)row0 * QKVS + col) =
                    pack_f16x2(acc[mi][nj][0], acc[mi][nj][1]);
                *(uint32_t*)(Cq + (size_t)(row0 + 8) * QKVS + col) =
                    pack_f16x2(acc[mi][nj][2], acc[mi][nj][3]);
            }
        }
    }
}

// ---------------------------------------------------------------------------
// FP16 tensor-core GEMM, fp32 out (out-projection). Unchanged from R14.
// ---------------------------------------------------------------------------
#define HG_STAGE_WORDS (128 * 36)
#define HG_SMEM_BYTES  (4 * HG_STAGE_WORDS * 4 * 2)   // 73728

__global__ __launch_bounds__(256, 2) void hgemm_f32(
    const __half* __restrict__ A, const __half* __restrict__ B,
    float* __restrict__ C, int M, int N, int K)
{
    extern __shared__ uint32_t sm[];
    const int tid  = threadIdx.x;
    const int brow = blockIdx.y * 128;
    const int bcol = blockIdx.x * 128;
    const int warp = tid >> 5;
    const int lane = tid & 31;
    const int g    = lane >> 2;
    const int tig  = lane & 3;
    const int warpM = (warp >> 1) * 32;
    const int warpN = (warp & 1) * 64;
    const int nslab = K >> 6;

    const uint32_t sa = smem_u32(sm);
    const uint32_t aab = sa + 4u * ((warpM + (lane & 15)) * 36 + ((lane >> 4) << 2));
    const uint32_t bbb = sa + 4u * (HG_STAGE_WORDS
                       + (warpN + (lane & 7) + ((lane >> 4) << 3)) * 36
                       + (((lane >> 3) & 1) << 2));

    auto As_w = [&](int st, int r, int w) -> uint32_t& {
        return sm[st * 2 * HG_STAGE_WORDS + r * 36 + w];
    };
    auto Bs_w = [&](int st, int r, int w) -> uint32_t& {
        return sm[st * 2 * HG_STAGE_WORDS + HG_STAGE_WORDS + r * 36 + w];
    };

    auto load_slab = [&](int j, int st) {
        const int k0 = j << 6;
#pragma unroll
        for (int i = 0; i < 4; i++) {
            int id  = tid + i * 256;
            int row = id >> 3;
            int g8  = (id & 7) * 8;
            cp_async16(smem_u32(&As_w(st, row, g8 >> 1)),
                       A + (size_t)(brow + row) * K + k0 + g8);
            cp_async16(smem_u32(&Bs_w(st, row, g8 >> 1)),
                       B + (size_t)(bcol + row) * K + k0 + g8);
        }
    };

    float acc[2][8][4];
#pragma unroll
    for (int mi = 0; mi < 2; mi++)
#pragma unroll
        for (int nj = 0; nj < 8; nj++)
#pragma unroll
            for (int c = 0; c < 4; c++) acc[mi][nj][c] = 0.f;

    load_slab(0, 0);
    cp_commit();

    for (int j = 0; j < nslab; j++) {
        const int st = j & 1;
        if (j + 1 < nslab) load_slab(j + 1, st ^ 1);
        cp_commit();
        cp_wait1();
        __syncthreads();

        const uint32_t stoff = (uint32_t)st * (2 * HG_STAGE_WORDS * 4);
#pragma unroll
        for (int ks = 0; ks < 32; ks += 8) {
            uint32_t af[2][4];
            uint32_t bf[8][2];
            LDSM_X4(af[0][0], af[0][1], af[0][2], af[0][3],
                    aab + stoff + 4u * ks);
            LDSM_X4(af[1][0], af[1][1], af[1][2], af[1][3],
                    aab + stoff + 4u * (16 * 36) + 4u * ks);
#pragma unroll
            for (int njp = 0; njp < 4; njp++)
                LDSM_X4(bf[2 * njp][0], bf[2 * njp][1],
                        bf[2 * njp + 1][0], bf[2 * njp + 1][1],
                        bbb + stoff + (uint32_t)njp * (16 * 36 * 4) + 4u * ks);
#pragma unroll
            for (int mi = 0; mi < 2; mi++)
#pragma unroll
                for (int nj = 0; nj < 8; nj++)
                    MMA_F16(acc[mi][nj][0], acc[mi][nj][1],
                            acc[mi][nj][2], acc[mi][nj][3],
                            af[mi][0], af[mi][1], af[mi][2], af[mi][3],
                            bf[nj][0], bf[nj][1]);
        }
        __syncthreads();
    }

#pragma unroll
    for (int mi = 0; mi < 2; mi++) {
        int row0 = brow + warpM + mi * 16 + g;
#pragma unroll
        for (int nj = 0; nj < 8; nj++) {
            int col = bcol + warpN + nj * 8 + tig * 2;
            float2 lo, hi;
            lo.x = acc[mi][nj][0]; lo.y = acc[mi][nj][1];
            hi.x = acc[mi][nj][2]; hi.y = acc[mi][nj][3];
            *(float2*)(C + (size_t)row0 * N + col)       = lo;
            *(float2*)(C + (size_t)(row0 + 8) * N + col) = hi;
        }
    }
}

// ---------------------------------------------------------------------------
// Flash attention, GQA K/V-sharing, fixed-max softmax. Unchanged from R14.
// ---------------------------------------------------------------------------
#define QK_PW 132
#define VT_PW 264
#define P_PW  36
#define ATTN_SMEM_WORDS (2*64*QK_PW + 64*QK_PW + 32*VT_PW + 2*64*P_PW + 2*128)
#define ATTN_SMEM_BYTES (ATTN_SMEM_WORDS * 4)   // 154112 B

__global__ __launch_bounds__(512, 1) void attn_f16(
    const __half* __restrict__ qkv, __half* __restrict__ yh)
{
    extern __shared__ uint32_t smw[];
    uint32_t* Qs = smw;                       // [2][64][132]
    uint32_t* Ks = Qs + 2 * 64 * QK_PW;       // [64][132]  (shared)
    uint32_t* Vt = Ks + 64 * QK_PW;           // [32][264]  (shared)
    uint32_t* Ps = Vt + 32 * VT_PW;           // [2][64][36]
    float* l2 = (float*)(Ps + 2 * 64 * P_PW); // [2][64][2]

    const int tid  = threadIdx.x;
    const int qb   = gridDim.x - 1 - blockIdx.x;
    const int kvi  = blockIdx.y;
    const int warp = tid >> 5;
    const int lane = tid & 31;
    const int g    = lane >> 2;
    const int tig  = lane & 3;
    const int wg   = warp >> 3;
    const int w8   = warp & 7;
    const int wn   = w8 & 1;
    const int r0   = (w8 >> 1) * 16 + g;
    const int h    = kvi * 2 + wg;

    const uint32_t q_lb = smem_u32(Qs + wg * 64 * QK_PW) +
        4u * (((w8 >> 1) * 16 + (lane & 15)) * QK_PW + ((lane >> 4) << 2));
    const uint32_t k_lb = smem_u32(Ks) +
        4u * ((wn * 32 + (lane & 7) + ((lane >> 4) << 3)) * QK_PW
              + (((lane >> 3) & 1) << 2));
    const uint32_t p_lb = smem_u32(Ps + wg * 64 * P_PW) +
        4u * (((w8 >> 1) * 16 + (lane & 15)) * P_PW + ((lane >> 4) << 2));

#pragma unroll
    for (int it = 0; it < 8; it++) {
        int idx = tid + it * 512;
        int wq = idx >> 11;
        int r  = (idx >> 5) & 63, c = idx & 31;
        uint4 o = *(const uint4*)(qkv + (size_t)(qb * 64 + r) * QKVS
                                  + (kvi * 2 + wq) * HD + c * 8);
        *(uint4*)&Qs[wq * 64 * QK_PW + r * QK_PW + c * 4] = o;
    }

    float acc[16][4];
#pragma unroll
    for (int nj = 0; nj < 16; nj++)
#pragma unroll
        for (int c = 0; c < 4; c++) acc[nj][c] = 0.f;

    float rsum0 = 0.f, rsum1 = 0.f;

    int s0 = qb * 64 - (WIN - 1);
    if (s0 < 0) s0 = 0;
    const int kt0 = s0 >> 6;
    const int qi0 = qb * 64 + r0;
    const int qi1 = qi0 + 8;

    for (int kt = kt0; kt <= qb; kt++) {
        const bool edge = (kt == qb) || (kt == kt0);
        __syncthreads();

#pragma unroll
        for (int it = 0; it < 4; it++) {
            int idx = tid + it * 512;
            int r = idx >> 5, c = idx & 31;
            uint4 o = *(const uint4*)(qkv + (size_t)(kt * 64 + r) * QKVS
                                      + 2048 + kvi * HD + c * 8);
            *(uint4*)&Ks[r * QK_PW + c * 4] = o;
        }
#pragma unroll
        for (int it = 0; it < 2; it++) {
            int idx = tid + it * 512;
            int kp = idx >> 5, dg = (idx & 31) * 8;
            const __half* v0p = qkv + (size_t)(kt * 64 + 2 * kp) * QKVS
                                + 3072 + kvi * HD + dg;
            uint4 A = *(const uint4*)v0p;
            uint4 B = *(const uint4*)(v0p + QKVS);
            uint32_t* dst = &Vt[kp * VT_PW + dg];
            dst[0] = __byte_perm(A.x, B.x, 0x5410);
            dst[1] = __byte_perm(A.x, B.x, 0x7632);
            dst[2] = __byte_perm(A.y, B.y, 0x5410);
            dst[3] = __byte_perm(A.y, B.y, 0x7632);
            dst[4] = __byte_perm(A.z, B.z, 0x5410);
            dst[5] = __byte_perm(A.z, B.z, 0x7632);
            dst[6] = __byte_perm(A.w, B.w, 0x5410);
            dst[7] = __byte_perm(A.w, B.w, 0x7632);
        }
        __syncthreads();

        float sfr[4][4];
#pragma unroll
        for (int nj = 0; nj < 4; nj++)
#pragma unroll
            for (int c = 0; c < 4; c++) sfr[nj][c] = 0.f;
#pragma unroll
        for (int ks = 0; ks < 128; ks += 8) {
            uint32_t a0, a1, a2, a3;
            LDSM_X4(a0, a1, a2, a3, q_lb + 4u * ks);
#pragma unroll
            for (int njp = 0; njp < 2; njp++) {
                uint32_t b00, b01, b10, b11;
                LDSM_X4(b00, b01, b10, b11,
                        k_lb + (uint32_t)njp * (16 * QK_PW * 4) + 4u * ks);
                MMA_F16(sfr[2*njp][0], sfr[2*njp][1], sfr[2*njp][2], sfr[2*njp][3],
                        a0, a1, a2, a3, b00, b01);
                MMA_F16(sfr[2*njp+1][0], sfr[2*njp+1][1], sfr[2*njp+1][2], sfr[2*njp+1][3],
                        a0, a1, a2, a3, b10, b11);
            }
        }

        uint32_t* Pw = Ps + wg * 64 * P_PW;
#pragma unroll
        for (int nj = 0; nj < 4; nj++) {
            float p00, p01, p10, p11;
            if (edge) {
                int colb = kt * 64 + wn * 32 + nj * 8 + 2 * tig;
                float v00 = sfr[nj][0] * 0.0625f;
                float v01 = sfr[nj][1] * 0.0625f;
                float v10 = sfr[nj][2] * 0.0625f;
                float v11 = sfr[nj][3] * 0.0625f;
                v00 = (colb     <= qi0 && colb     > qi0 - WIN) ? v00 : -INFINITY;
                v01 = (colb + 1 <= qi0 && colb + 1 > qi0 - WIN) ? v01 : -INFINITY;
                v10 = (colb     <= qi1 && colb     > qi1 - WIN) ? v10 : -INFINITY;
                v11 = (colb + 1 <= qi1 && colb + 1 > qi1 - WIN) ? v11 : -INFINITY;
                p00 = __expf(v00 - SMAX);
                p01 = __expf(v01 - SMAX);
                p10 = __expf(v10 - SMAX);
                p11 = __expf(v11 - SMAX);
            } else {
                p00 = __expf(fmaf(sfr[nj][0], 0.0625f, -SMAX));
                p01 = __expf(fmaf(sfr[nj][1], 0.0625f, -SMAX));
                p10 = __expf(fmaf(sfr[nj][2], 0.0625f, -SMAX));
                p11 = __expf(fmaf(sfr[nj][3], 0.0625f, -SMAX));
            }
            rsum0 += p00 + p01;
            rsum1 += p10 + p11;
            int wd = wn * 16 + nj * 4 + tig;
            Pw[r0 * P_PW + wd]       = pack_f16x2(p00, p01);
            Pw[(r0 + 8) * P_PW + wd] = pack_f16x2(p10, p11);
        }
        __syncthreads();

#pragma unroll
        for (int ks = 0; ks < 32; ks += 8) {
            uint32_t a0, a1, a2, a3;
            LDSM_X4(a0, a1, a2, a3, p_lb + 4u * ks);
#pragma unroll
            for (int nj = 0; nj < 16; nj++) {
                int c = wn * 128 + nj * 8 + g;
                uint32_t b0 = Vt[(ks + tig) * VT_PW + c];
                uint32_t b1 = Vt[(ks + tig + 4) * VT_PW + c];
                MMA_F16(acc[nj][0], acc[nj][1], acc[nj][2], acc[nj][3],
                        a0, a1, a2, a3, b0, b1);
            }
        }
    }

#pragma unroll
    for (int o = 1; o <= 2; o <<= 1) {
        rsum0 += __shfl_xor_sync(0xffffffffu, rsum0, o);
        rsum1 += __shfl_xor_sync(0xffffffffu, rsum1, o);
    }
    float* l2w = l2 + wg * 128;
    if (tig == 0) {
        l2w[r0 * 2 + wn]       = rsum0;
        l2w[(r0 + 8) * 2 + wn] = rsum1;
    }
    __syncthreads();
    float inv0 = 1.f / (l2w[r0 * 2]       + l2w[r0 * 2 + 1]);
    float inv1 = 1.f / (l2w[(r0 + 8) * 2] + l2w[(r0 + 8) * 2 + 1]);

    __half* yr0 = yh + (size_t)(qb * 64 + r0) * DM + h * HD;
    __half* yr1 = yh + (size_t)(qb * 64 + r0 + 8) * DM + h * HD;
#pragma unroll
    for (int nj = 0; nj < 16; nj++) {
        int col = wn * 128 + nj * 8 + 2 * tig;
        *(uint32_t*)(yr0 + col) = pack_f16x2(acc[nj][0] * inv0, acc[nj][1] * inv0);
        *(uint32_t*)(yr1 + col) = pack_f16x2(acc[nj][2] * inv1, acc[nj][3] * inv1);
    }
}

// ---------------------------------------------------------------------------
extern "C" void kernel_launch(void* const* d_in, const int* in_sizes, int n_in,
                              void* d_out, int out_size)
{
    const float* x  = (const float*)d_in[0];
    const int*   pos= (const int*)  d_in[1];
    const float* Wq = (const float*)d_in[2];
    const float* Wk = (const float*)d_in[3];
    const float* Wv = (const float*)d_in[4];
    const float* Wo = (const float*)d_in[5];
    const float* qw = (const float*)d_in[6];
    const float* kw = (const float*)d_in[7];
    float* out = (float*)d_out;

    float  *cs_p, *sn_p;
    __half *qkvh_p, *xh_p, *wqkvh_p, *woh_p, *yh_p;
    cudaGetSymbolAddress((void**)&qkvh_p,  g_qkvh);
    cudaGetSymbolAddress((void**)&cs_p,    g_cs);
    cudaGetSymbolAddress((void**)&sn_p,    g_sn);
    cudaGetSymbolAddress((void**)&xh_p,    g_xh);
    cudaGetSymbolAddress((void**)&wqkvh_p, g_wqkvh);
    cudaGetSymbolAddress((void**)&woh_p,   g_woh);
    cudaGetSymbolAddress((void**)&yh_p,    g_yh);

    // fp32->fp16 converts + rope table (one launch)
    prep_kernel<<<PREP_BLOCKS, 256>>>(x, Wq, Wk, Wv, Wo, pos,
                                      xh_p, wqkvh_p, woh_p, cs_p, sn_p);

    cudaFuncSetAttribute(qkv_gemm_fused, cudaFuncAttributeMaxDynamicSharedMemorySize,
                         QG_SMEM_BYTES);
    cudaFuncSetAttribute(hgemm_f32, cudaFuncAttributeMaxDynamicSharedMemorySize,
                         HG_SMEM_BYTES);

    // Fused QKV projection + RMSNorm + RoPE (one launch, fp16 out)
    qkv_gemm_fused<<<dim3(QKVS / 256, T_SEQ / 128), 512, QG_SMEM_BYTES>>>(
        xh_p, wqkvh_p, qkvh_p, qw, kw, cs_p, sn_p);

    // Flash attention (GQA K/V sharing)
    cudaFuncSetAttribute(attn_f16, cudaFuncAttributeMaxDynamicSharedMemorySize,
                         ATTN_SMEM_BYTES);
    attn_f16<<<dim3(T_SEQ / 64, NKV), 512, ATTN_SMEM_BYTES>>>(qkvh_p, yh_p);

    // Output projection (fp32 out -> d_out)
    hgemm_f32<<<dim3(DM / 128, T_SEQ / 128), 256, HG_SMEM_BYTES>>>(
        yh_p, woh_p, out, T_SEQ, DM, DM);
}

// round 17
// speedup vs baseline: 1.5359x; 1.5359x over previous
#include <cuda_runtime.h>
#include <cuda_bf16.h>
#include <cuda_fp16.h>
#include <math.h>
#include <stdint.h>

#define T_SEQ 4096
#define DM    2048
#define NH    8
#define NKV   4
#define HD    256
#define WIN   1024
#define QKVS  4096     // fused row: Q[0,2048) | K[2048,3072) | V[3072,4096)
#define SMAX  8.0f     // fixed softmax max: |s| <= 16 provable, exp(16-8) < fp16 max

// Scratch (static __device__ arrays — allocation-free per harness rules)
__device__ __half g_qkvh[T_SEQ * QKVS];       // 32 MB fused QKV (fp16)
__device__ __half g_xh[T_SEQ * DM];           // 16 MB
__device__ __half g_wqkvh[QKVS * DM];         // 16 MB [Wq; Wk; Wv]
__device__ __half g_woh[DM * DM];             // 8 MB
__device__ __half g_yh[T_SEQ * DM];           // 16 MB (attention out, fp16)
__device__ float  g_cs[T_SEQ * 128];          // rope cos table
__device__ float  g_sn[T_SEQ * 128];          // rope sin table

__device__ __forceinline__ uint32_t pack_f16x2(float lo, float hi) {
    __half2 h = __floats2half2_rn(lo, hi);    // .x = lo (low 16 bits)
    return *reinterpret_cast<uint32_t*>(&h);
}

__device__ __forceinline__ uint32_t smem_u32(const void* p) {
    uint32_t a;
    asm("{ .reg .u64 t; cvta.to.shared.u64 t, %1; cvt.u32.u64 %0, t; }"
        : "=r"(a) : "l"(p));
    return a;
}
__device__ __forceinline__ void cp_async16(uint32_t dst, const void* src) {
    asm volatile("cp.async.cg.shared.global [%0], [%1], 16;" :: "r"(dst), "l"(src));
}
__device__ __forceinline__ void cp_commit() {
    asm volatile("cp.async.commit_group;" ::: "memory");
}
__device__ __forceinline__ void cp_wait1() {
    asm volatile("cp.async.wait_group 1;" ::: "memory");
}

#define MMA_F16(d0,d1,d2,d3,a0,a1,a2,a3,b0,b1)                               \
    asm volatile(                                                            \
        "mma.sync.aligned.m16n8k16.row.col.f32.f16.f16.f32 "                 \
        "{%0,%1,%2,%3}, {%4,%5,%6,%7}, {%8,%9}, {%0,%1,%2,%3};"              \
        : "+f"(d0), "+f"(d1), "+f"(d2), "+f"(d3)                             \
        : "r"(a0), "r"(a1), "r"(a2), "r"(a3), "r"(b0), "r"(b1))

#define LDSM_X4(r0,r1,r2,r3,addr)                                            \
    asm volatile("ldmatrix.sync.aligned.m8n8.x4.shared.b16 {%0,%1,%2,%3}, [%4];" \
        : "=r"(r0), "=r"(r1), "=r"(r2), "=r"(r3) : "r"(addr))

// ---------------------------------------------------------------------------
// ONE kernel: fp32->fp16 convert of x/Wq/Wk/Wv/Wo  +  rope cos/sin table.
// Blocks [0, CONV_BLOCKS) convert; blocks beyond build the table (2 t each).
// ---------------------------------------------------------------------------
#define NX   (T_SEQ * DM)
#define NWQ  (DM * DM)
#define NWK  (NKV * HD * DM)
#define NWV  (NKV * HD * DM)
#define NWO  (DM * DM)
#define NTOT (NX + NWQ + NWK + NWV + NWO)
#define CONV_BLOCKS 2048
#define PREP_BLOCKS (CONV_BLOCKS + T_SEQ / 2)

__global__ __launch_bounds__(256) void prep_kernel(
    const float* __restrict__ x,  const float* __restrict__ Wq,
    const float* __restrict__ Wk, const float* __restrict__ Wv,
    const float* __restrict__ Wo, const int* __restrict__ pos,
    __half* __restrict__ xh, __half* __restrict__ wqkvh,
    __half* __restrict__ woh, float* __restrict__ cs, float* __restrict__ sn)
{
    if (blockIdx.x < CONV_BLOCKS) {
        for (size_t i = ((size_t)blockIdx.x * 256 + threadIdx.x) * 8; i < NTOT;
             i += (size_t)CONV_BLOCKS * 256 * 8) {
            const float* src;
            __half* dst;
            size_t o = i;
            if (o < NX)                { src = x;  dst = xh; }
            else if ((o -= NX)  < NWQ) { src = Wq; dst = wqkvh; }
            else if ((o -= NWQ) < NWK) { src = Wk; dst = wqkvh + NWQ; }
            else if ((o -= NWK) < NWV) { src = Wv; dst = wqkvh + NWQ + NWK; }
            else { o -= NWV;             src = Wo; dst = woh; }
            float4 v0 = *(const float4*)(src + o);
            float4 v1 = *(const float4*)(src + o + 4);
            uint4 ov;
            ov.x = pack_f16x2(v0.x, v0.y);
            ov.y = pack_f16x2(v0.z, v0.w);
            ov.z = pack_f16x2(v1.x, v1.y);
            ov.w = pack_f16x2(v1.z, v1.w);
            *(uint4*)((char*)dst + o * 2) = ov;
        }
    } else {
        int b = blockIdx.x - CONV_BLOCKS;
        int t = b * 2 + (threadIdx.x >> 7);
        int f = threadIdx.x & 127;
        float inv_freq = expf(-(float)f * (logf(10000.0f) / 128.0f));
        float ang = (float)pos[t] * inv_freq;
        float sv, cv;
        sincosf(ang, &sv, &cv);
        cs[t * 128 + f] = cv;
        sn[t * 128 + f] = sv;
    }
}

// ---------------------------------------------------------------------------
// FP16 tensor-core GEMM core (fp32 accum). 128x128 tile, BK=64 halves,
// cp.async double buffered, ldmatrix fragments, 8 warps (4m x 2n).
// Template-shared body (identical to the R14 build that achieved 2 CTAs/SM).
// ---------------------------------------------------------------------------
#define HG_STAGE_WORDS (128 * 36)
#define HG_SMEM_BYTES  (4 * HG_STAGE_WORDS * 4 * 2)   // 73728

template <bool HalfOut>
__device__ __forceinline__ void hgemm_body(
    const __half* __restrict__ A, const __half* __restrict__ B,
    void* __restrict__ C, int M, int N, int K)
{
    extern __shared__ uint32_t sm[];
    const int tid  = threadIdx.x;
    const int brow = blockIdx.y * 128;
    const int bcol = blockIdx.x * 128;
    const int warp = tid >> 5;
    const int lane = tid & 31;
    const int g    = lane >> 2;
    const int tig  = lane & 3;
    const int warpM = (warp >> 1) * 32;
    const int warpN = (warp & 1) * 64;
    const int nslab = K >> 6;

    const uint32_t sa = smem_u32(sm);
    const uint32_t aab = sa + 4u * ((warpM + (lane & 15)) * 36 + ((lane >> 4) << 2));
    const uint32_t bbb = sa + 4u * (HG_STAGE_WORDS
                       + (warpN + (lane & 7) + ((lane >> 4) << 3)) * 36
                       + (((lane >> 3) & 1) << 2));

    auto As_w = [&](int st, int r, int w) -> uint32_t& {
        return sm[st * 2 * HG_STAGE_WORDS + r * 36 + w];
    };
    auto Bs_w = [&](int st, int r, int w) -> uint32_t& {
        return sm[st * 2 * HG_STAGE_WORDS + HG_STAGE_WORDS + r * 36 + w];
    };

    auto load_slab = [&](int j, int st) {
        const int k0 = j << 6;
#pragma unroll
        for (int i = 0; i < 4; i++) {
            int id  = tid + i * 256;
            int row = id >> 3;
            int g8  = (id & 7) * 8;
            cp_async16(smem_u32(&As_w(st, row, g8 >> 1)),
                       A + (size_t)(brow + row) * K + k0 + g8);
            cp_async16(smem_u32(&Bs_w(st, row, g8 >> 1)),
                       B + (size_t)(bcol + row) * K + k0 + g8);
        }
    };

    float acc[2][8][4];
#pragma unroll
    for (int mi = 0; mi < 2; mi++)
#pragma unroll
        for (int nj = 0; nj < 8; nj++)
#pragma unroll
            for (int c = 0; c < 4; c++) acc[mi][nj][c] = 0.f;

    load_slab(0, 0);
    cp_commit();

    for (int j = 0; j < nslab; j++) {
        const int st = j & 1;
        if (j + 1 < nslab) load_slab(j + 1, st ^ 1);
        cp_commit();
        cp_wait1();
        __syncthreads();

        const uint32_t stoff = (uint32_t)st * (2 * HG_STAGE_WORDS * 4);
#pragma unroll
        for (int ks = 0; ks < 32; ks += 8) {
            uint32_t af[2][4];
            uint32_t bf[8][2];
            LDSM_X4(af[0][0], af[0][1], af[0][2], af[0][3],
                    aab + stoff + 4u * ks);
            LDSM_X4(af[1][0], af[1][1], af[1][2], af[1][3],
                    aab + stoff + 4u * (16 * 36) + 4u * ks);
#pragma unroll
            for (int njp = 0; njp < 4; njp++)
                LDSM_X4(bf[2 * njp][0], bf[2 * njp][1],
                        bf[2 * njp + 1][0], bf[2 * njp + 1][1],
                        bbb + stoff + (uint32_t)njp * (16 * 36 * 4) + 4u * ks);
#pragma unroll
            for (int mi = 0; mi < 2; mi++)
#pragma unroll
                for (int nj = 0; nj < 8; nj++)
                    MMA_F16(acc[mi][nj][0], acc[mi][nj][1],
                            acc[mi][nj][2], acc[mi][nj][3],
                            af[mi][0], af[mi][1], af[mi][2], af[mi][3],
                            bf[nj][0], bf[nj][1]);
        }
        __syncthreads();
    }

#pragma unroll
    for (int mi = 0; mi < 2; mi++) {
        int row0 = brow + warpM + mi * 16 + g;
#pragma unroll
        for (int nj = 0; nj < 8; nj++) {
            int col = bcol + warpN + nj * 8 + tig * 2;
            if (HalfOut) {
                __half* Ch = (__half*)C;
                *(uint32_t*)(Ch + (size_t)row0 * N + col) =
                    pack_f16x2(acc[mi][nj][0], acc[mi][nj][1]);
                *(uint32_t*)(Ch + (size_t)(row0 + 8) * N + col) =
                    pack_f16x2(acc[mi][nj][2], acc[mi][nj][3]);
            } else {
                float* Cf = (float*)C;
                float2 lo, hi;
                lo.x = acc[mi][nj][0]; lo.y = acc[mi][nj][1];
                hi.x = acc[mi][nj][2]; hi.y = acc[mi][nj][3];
                *(float2*)(Cf + (size_t)row0 * N + col)       = lo;
                *(float2*)(Cf + (size_t)(row0 + 8) * N + col) = hi;
            }
        }
    }
}

__global__ __launch_bounds__(256, 2) void hgemm_f32(
    const __half* __restrict__ A, const __half* __restrict__ B,
    float* __restrict__ C, int M, int N, int K)
{
    hgemm_body<false>(A, B, C, M, N, K);
}

__global__ __launch_bounds__(256, 2) void hgemm_f16(
    const __half* __restrict__ A, const __half* __restrict__ B,
    __half* __restrict__ C, int M, int N, int K)
{
    hgemm_body<true>(A, B, C, M, N, K);
}

// ---------------------------------------------------------------------------
// Warp-per-head RMSNorm + RoPE, in place on fp16 fused QKV buffer.
// ---------------------------------------------------------------------------
__global__ __launch_bounds__(384) void rmsnorm_rope_kernel(
    __half* __restrict__ qkv,
    const float* __restrict__ qw, const float* __restrict__ kw,
    const float* __restrict__ cs, const float* __restrict__ sn_t)
{
    const int t    = blockIdx.x;
    const int w    = threadIdx.x >> 5;     // head index 0..11
    const int lane = threadIdx.x & 31;
    const int d0   = lane * 8;

    __half* row;
    const float* wgt;
    if (w < NH) { row = qkv + (size_t)t * QKVS + w * HD;               wgt = qw; }
    else        { row = qkv + (size_t)t * QKVS + 2048 + (w - NH) * HD; wgt = kw; }

    uint4 wv = *(const uint4*)(row + d0);
    const uint32_t* wr = (const uint32_t*)&wv;
    float e[8];
#pragma unroll
    for (int j = 0; j < 4; j++) {
        __half2 h = *(const __half2*)&wr[j];
        float2 f = __half22float2(h);
        e[2 * j]     = f.x;
        e[2 * j + 1] = f.y;
    }

    float ss = 0.f;
#pragma unroll
    for (int j = 0; j < 8; j++) ss += e[j] * e[j];
#pragma unroll
    for (int o = 16; o; o >>= 1) ss += __shfl_xor_sync(0xffffffffu, ss, o);
    float scale = rsqrtf(ss * (1.0f / HD) + 1e-6f);

    const int fb = d0 & 127;
    float4 w4[2], c4[2], s4[2];
    w4[0] = *(const float4*)(wgt + d0);          w4[1] = *(const float4*)(wgt + d0 + 4);
    c4[0] = *(const float4*)(cs  + t * 128 + fb); c4[1] = *(const float4*)(cs  + t * 128 + fb + 4);
    s4[0] = *(const float4*)(sn_t + t * 128 + fb); s4[1] = *(const float4*)(sn_t + t * 128 + fb + 4);
    const float* wf = (const float*)w4;
    const float* cf = (const float*)c4;
    const float* sf = (const float*)s4;

    uint4 ov;
    uint32_t* orp = (uint32_t*)&ov;
#pragma unroll
    for (int j = 0; j < 4; j++) {
        float n0 = e[2 * j]     * scale * wf[2 * j];
        float n1 = e[2 * j + 1] * scale * wf[2 * j + 1];
        float r0 = n0 * cf[2 * j]     - n1 * sf[2 * j];
        float r1 = n1 * cf[2 * j + 1] + n0 * sf[2 * j + 1];
        orp[j] = pack_f16x2(r0, r1);
    }
    *(uint4*)(row + d0) = ov;
}

// ---------------------------------------------------------------------------
// Flash attention, GQA K/V-sharing: one block = 64 queries x 1 KV group
// (= 2 q-heads). 512 threads = 2 warp-groups of 8 warps; each warp-group runs
// the proven 8-warp layout on its own Q/P while SHARING the K/V smem tiles.
// Fixed-max softmax, fp16 data path, 1 CTA/SM (16 warps/SM).
// ---------------------------------------------------------------------------
#define QK_PW 132
#define VT_PW 264
#define P_PW  36
#define ATTN_SMEM_WORDS (2*64*QK_PW + 64*QK_PW + 32*VT_PW + 2*64*P_PW + 2*128)
#define ATTN_SMEM_BYTES (ATTN_SMEM_WORDS * 4)   // 154112 B

__global__ __launch_bounds__(512, 1) void attn_f16(
    const __half* __restrict__ qkv, __half* __restrict__ yh)
{
    extern __shared__ uint32_t smw[];
    uint32_t* Qs = smw;                       // [2][64][132]
    uint32_t* Ks = Qs + 2 * 64 * QK_PW;       // [64][132]  (shared)
    uint32_t* Vt = Ks + 64 * QK_PW;           // [32][264]  (shared)
    uint32_t* Ps = Vt + 32 * VT_PW;           // [2][64][36]
    float* l2 = (float*)(Ps + 2 * 64 * P_PW); // [2][64][2]

    const int tid  = threadIdx.x;
    const int qb   = gridDim.x - 1 - blockIdx.x;   // longest-first scheduling
    const int kvi  = blockIdx.y;
    const int warp = tid >> 5;
    const int lane = tid & 31;
    const int g    = lane >> 2;
    const int tig  = lane & 3;
    const int wg   = warp >> 3;            // warp-group = q-head within pair
    const int w8   = warp & 7;
    const int wn   = w8 & 1;
    const int r0   = (w8 >> 1) * 16 + g;
    const int h    = kvi * 2 + wg;

    const uint32_t q_lb = smem_u32(Qs + wg * 64 * QK_PW) +
        4u * (((w8 >> 1) * 16 + (lane & 15)) * QK_PW + ((lane >> 4) << 2));
    const uint32_t k_lb = smem_u32(Ks) +
        4u * ((wn * 32 + (lane & 7) + ((lane >> 4) << 3)) * QK_PW
              + (((lane >> 3) & 1) << 2));
    const uint32_t p_lb = smem_u32(Ps + wg * 64 * P_PW) +
        4u * (((w8 >> 1) * 16 + (lane & 15)) * P_PW + ((lane >> 4) << 2));

    // Q tiles for both heads: raw copy (2 x 64 rows x 32 uint4 over 512 thr)
#pragma unroll
    for (int it = 0; it < 8; it++) {
        int idx = tid + it * 512;             // 0..4095
        int wq = idx >> 11;                   // head-in-pair
        int r  = (idx >> 5) & 63, c = idx & 31;
        uint4 o = *(const uint4*)(qkv + (size_t)(qb * 64 + r) * QKVS
                                  + (kvi * 2 + wq) * HD + c * 8);
        *(uint4*)&Qs[wq * 64 * QK_PW + r * QK_PW + c * 4] = o;
    }

    float acc[16][4];
#pragma unroll
    for (int nj = 0; nj < 16; nj++)
#pragma unroll
        for (int c = 0; c < 4; c++) acc[nj][c] = 0.f;

    float rsum0 = 0.f, rsum1 = 0.f;

    int s0 = qb * 64 - (WIN - 1);
    if (s0 < 0) s0 = 0;
    const int kt0 = s0 >> 6;
    const int qi0 = qb * 64 + r0;
    const int qi1 = qi0 + 8;

    for (int kt = kt0; kt <= qb; kt++) {
        const bool edge = (kt == qb) || (kt == kt0);
        __syncthreads();   // previous tile's smem reads done

        // K tile: raw copy (2048 uint4 over 512 threads)
#pragma unroll
        for (int it = 0; it < 4; it++) {
            int idx = tid + it * 512;
            int r = idx >> 5, c = idx & 31;
            uint4 o = *(const uint4*)(qkv + (size_t)(kt * 64 + r) * QKVS
                                      + 2048 + kvi * HD + c * 8);
            *(uint4*)&Ks[r * QK_PW + c * 4] = o;
        }
        // V tile: row-pair interleave via prmt (1024 chunks over 512 threads)
#pragma unroll
        for (int it = 0; it < 2; it++) {
            int idx = tid + it * 512;
            int kp = idx >> 5, dg = (idx & 31) * 8;
            const __half* v0p = qkv + (size_t)(kt * 64 + 2 * kp) * QKVS
                                + 3072 + kvi * HD + dg;
            uint4 A = *(const uint4*)v0p;
            uint4 B = *(const uint4*)(v0p + QKVS);
            uint32_t* dst = &Vt[kp * VT_PW + dg];
            dst[0] = __byte_perm(A.x, B.x, 0x5410);
            dst[1] = __byte_perm(A.x, B.x, 0x7632);
            dst[2] = __byte_perm(A.y, B.y, 0x5410);
            dst[3] = __byte_perm(A.y, B.y, 0x7632);
            dst[4] = __byte_perm(A.z, B.z, 0x5410);
            dst[5] = __byte_perm(A.z, B.z, 0x7632);
            dst[6] = __byte_perm(A.w, B.w, 0x5410);
            dst[7] = __byte_perm(A.w, B.w, 0x7632);
        }
        __syncthreads();   // tiles resident

        // ---- S = Q @ K^T (per warp-group on its own Q) ----
        float sfr[4][4];
#pragma unroll
        for (int nj = 0; nj < 4; nj++)
#pragma unroll
            for (int c = 0; c < 4; c++) sfr[nj][c] = 0.f;
#pragma unroll
        for (int ks = 0; ks < 128; ks += 8) {
            uint32_t a0, a1, a2, a3;
            LDSM_X4(a0, a1, a2, a3, q_lb + 4u * ks);
#pragma unroll
            for (int njp = 0; njp < 2; njp++) {
                uint32_t b00, b01, b10, b11;
                LDSM_X4(b00, b01, b10, b11,
                        k_lb + (uint32_t)njp * (16 * QK_PW * 4) + 4u * ks);
                MMA_F16(sfr[2*njp][0], sfr[2*njp][1], sfr[2*njp][2], sfr[2*njp][3],
                        a0, a1, a2, a3, b00, b01);
                MMA_F16(sfr[2*njp+1][0], sfr[2*njp+1][1], sfr[2*njp+1][2], sfr[2*njp+1][3],
                        a0, a1, a2, a3, b10, b11);
            }
        }

        // ---- fixed-max softmax: p = exp(s/16 - 8); masked -> 0 ----
        uint32_t* Pw = Ps + wg * 64 * P_PW;
#pragma unroll
        for (int nj = 0; nj < 4; nj++) {
            float p00, p01, p10, p11;
            if (edge) {
                int colb = kt * 64 + wn * 32 + nj * 8 + 2 * tig;
                float v00 = sfr[nj][0] * 0.0625f;
                float v01 = sfr[nj][1] * 0.0625f;
                float v10 = sfr[nj][2] * 0.0625f;
                float v11 = sfr[nj][3] * 0.0625f;
                v00 = (colb     <= qi0 && colb     > qi0 - WIN) ? v00 : -INFINITY;
                v01 = (colb + 1 <= qi0 && colb + 1 > qi0 - WIN) ? v01 : -INFINITY;
                v10 = (colb     <= qi1 && colb     > qi1 - WIN) ? v10 : -INFINITY;
                v11 = (colb + 1 <= qi1 && colb + 1 > qi1 - WIN) ? v11 : -INFINITY;
                p00 = __expf(v00 - SMAX);
                p01 = __expf(v01 - SMAX);
                p10 = __expf(v10 - SMAX);
                p11 = __expf(v11 - SMAX);
            } else {
                p00 = __expf(fmaf(sfr[nj][0], 0.0625f, -SMAX));
                p01 = __expf(fmaf(sfr[nj][1], 0.0625f, -SMAX));
                p10 = __expf(fmaf(sfr[nj][2], 0.0625f, -SMAX));
                p11 = __expf(fmaf(sfr[nj][3], 0.0625f, -SMAX));
            }
            rsum0 += p00 + p01;
            rsum1 += p10 + p11;
            int wd = wn * 16 + nj * 4 + tig;
            Pw[r0 * P_PW + wd]       = pack_f16x2(p00, p01);
            Pw[(r0 + 8) * P_PW + wd] = pack_f16x2(p10, p11);
        }
        __syncthreads();   // P ready for cross-warp ldmatrix

        // ---- O += P @ V ----
#pragma unroll
        for (int ks = 0; ks < 32; ks += 8) {
            uint32_t a0, a1, a2, a3;
            LDSM_X4(a0, a1, a2, a3, p_lb + 4u * ks);
#pragma unroll
            for (int nj = 0; nj < 16; nj++) {
                int c = wn * 128 + nj * 8 + g;
                uint32_t b0 = Vt[(ks + tig) * VT_PW + c];
                uint32_t b1 = Vt[(ks + tig + 4) * VT_PW + c];
                MMA_F16(acc[nj][0], acc[nj][1], acc[nj][2], acc[nj][3],
                        a0, a1, a2, a3, b0, b1);
            }
        }
    }

    // Final row-sum reduction per warp-group.
#pragma unroll
    for (int o = 1; o <= 2; o <<= 1) {
        rsum0 += __shfl_xor_sync(0xffffffffu, rsum0, o);
        rsum1 += __shfl_xor_sync(0xffffffffu, rsum1, o);
    }
    float* l2w = l2 + wg * 128;
    if (tig == 0) {
        l2w[r0 * 2 + wn]       = rsum0;
        l2w[(r0 + 8) * 2 + wn] = rsum1;
    }
    __syncthreads();
    float inv0 = 1.f / (l2w[r0 * 2]       + l2w[r0 * 2 + 1]);
    float inv1 = 1.f / (l2w[(r0 + 8) * 2] + l2w[(r0 + 8) * 2 + 1]);

    __half* yr0 = yh + (size_t)(qb * 64 + r0) * DM + h * HD;
    __half* yr1 = yh + (size_t)(qb * 64 + r0 + 8) * DM + h * HD;
#pragma unroll
    for (int nj = 0; nj < 16; nj++) {
        int col = wn * 128 + nj * 8 + 2 * tig;
        *(uint32_t*)(yr0 + col) = pack_f16x2(acc[nj][0] * inv0, acc[nj][1] * inv0);
        *(uint32_t*)(yr1 + col) = pack_f16x2(acc[nj][2] * inv1, acc[nj][3] * inv1);
    }
}

// ---------------------------------------------------------------------------
extern "C" void kernel_launch(void* const* d_in, const int* in_sizes, int n_in,
                              void* d_out, int out_size)
{
    const float* x  = (const float*)d_in[0];
    const int*   pos= (const int*)  d_in[1];
    const float* Wq = (const float*)d_in[2];
    const float* Wk = (const float*)d_in[3];
    const float* Wv = (const float*)d_in[4];
    const float* Wo = (const float*)d_in[5];
    const float* qw = (const float*)d_in[6];
    const float* kw = (const float*)d_in[7];
    float* out = (float*)d_out;

    float  *cs_p, *sn_p;
    __half *qkvh_p, *xh_p, *wqkvh_p, *woh_p, *yh_p;
    cudaGetSymbolAddress((void**)&qkvh_p,  g_qkvh);
    cudaGetSymbolAddress((void**)&cs_p,    g_cs);
    cudaGetSymbolAddress((void**)&sn_p,    g_sn);
    cudaGetSymbolAddress((void**)&xh_p,    g_xh);
    cudaGetSymbolAddress((void**)&wqkvh_p, g_wqkvh);
    cudaGetSymbolAddress((void**)&woh_p,   g_woh);
    cudaGetSymbolAddress((void**)&yh_p,    g_yh);

    // fp32->fp16 converts + rope table (one launch)
    prep_kernel<<<PREP_BLOCKS, 256>>>(x, Wq, Wk, Wv, Wo, pos,
                                      xh_p, wqkvh_p, woh_p, cs_p, sn_p);

    cudaFuncSetAttribute(hgemm_f32, cudaFuncAttributeMaxDynamicSharedMemorySize,
                         HG_SMEM_BYTES);
    cudaFuncSetAttribute(hgemm_f16, cudaFuncAttributeMaxDynamicSharedMemorySize,
                         HG_SMEM_BYTES);

    // Fused QKV projection: one launch, fp16 out
    hgemm_f16<<<dim3(QKVS / 128, T_SEQ / 128), 256, HG_SMEM_BYTES>>>(
        xh_p, wqkvh_p, qkvh_p, T_SEQ, QKVS, DM);

    // RMSNorm + RoPE: warp-per-head, in place on fp16 QKV
    rmsnorm_rope_kernel<<<T_SEQ, 384>>>(qkvh_p, qw, kw, cs_p, sn_p);

    // Flash attention (GQA K/V sharing: 64 queries x 1 KV group per block)
    cudaFuncSetAttribute(attn_f16, cudaFuncAttributeMaxDynamicSharedMemorySize,
                         ATTN_SMEM_BYTES);
    attn_f16<<<dim3(T_SEQ / 64, NKV), 512, ATTN_SMEM_BYTES>>>(qkvh_p, yh_p);

    // Output projection (fp32 out -> d_out)
    hgemm_f32<<<dim3(DM / 128, T_SEQ / 128), 256, HG_SMEM_BYTES>>>(
        yh_p, woh_p, out, T_SEQ, DM, DM);
}